// round 11
// baseline (speedup 1.0000x reference)
#include <cuda_runtime.h>
#include <cstdint>

#define B_  2
#define T_  2048
#define D_  2048
#define H_  32
#define HD_ 64
#define SCALE_ 0.125f   // 1/sqrt(64)

// ---------------- scratch (device globals: allocation-free) ----------------
__device__ float g_x [(size_t)B_ * T_ * D_];
__device__ float g_wq[(size_t)D_ * D_];
__device__ float g_wk[(size_t)D_ * D_];
__device__ float g_wv[(size_t)D_ * D_];
__device__ float g_wo[(size_t)D_ * D_];
__device__ float g_q [(size_t)B_ * H_ * T_ * HD_];
__device__ float g_k [(size_t)B_ * H_ * T_ * HD_];
__device__ float g_v [(size_t)B_ * H_ * T_ * HD_];
__device__ float g_ctx[(size_t)B_ * T_ * D_];

// ---------------- helpers ----------------
__device__ __forceinline__ float to_tf32(float x) {
    uint32_t u;
    asm("cvt.rna.tf32.f32 %0, %1;" : "=r"(u) : "f"(x));
    return __uint_as_float(u);
}

__device__ __forceinline__ void mma8(float* c, const uint32_t* a, const uint32_t* b) {
    asm volatile(
        "mma.sync.aligned.m16n8k8.row.col.f32.tf32.tf32.f32 "
        "{%0,%1,%2,%3},{%4,%5,%6,%7},{%8,%9},{%0,%1,%2,%3};\n"
        : "+f"(c[0]), "+f"(c[1]), "+f"(c[2]), "+f"(c[3])
        : "r"(a[0]), "r"(a[1]), "r"(a[2]), "r"(a[3]), "r"(b[0]), "r"(b[1]));
}

__device__ __forceinline__ void cp16(uint32_t saddr, const void* g) {
    asm volatile("cp.async.cg.shared.global [%0], [%1], 16;\n"
                 :: "r"(saddr), "l"(g) : "memory");
}
__device__ __forceinline__ void cp_commit() {
    asm volatile("cp.async.commit_group;\n" ::: "memory");
}
__device__ __forceinline__ void cp_wait0() {
    asm volatile("cp.async.wait_group 0;\n" ::: "memory");
}

// ============================================================================
// Pre-round+permute: per 8-float k-block, write tf32-rounded values in order
// (k0,k4,k1,k5,k2,k6,k3,k7). GEMM fragment pairs (k+tig, k+tig+4) become
// adjacent -> LDS.64 fragment loads.
// ============================================================================
__global__ __launch_bounds__(256) void round_perm_kernel(
    const float* __restrict__ in, float* __restrict__ out, int nblk)
{
    int i = blockIdx.x * 256 + threadIdx.x;
    if (i < nblk) {
        const float4* p = (const float4*)(in + (size_t)i * 8);
        float4 a = p[0], b = p[1];   // a = k0..k3, b = k4..k7
        float4 o0 = make_float4(to_tf32(a.x), to_tf32(b.x), to_tf32(a.y), to_tf32(b.y));
        float4 o1 = make_float4(to_tf32(a.z), to_tf32(b.z), to_tf32(a.w), to_tf32(b.w));
        float4* q = (float4*)(out + (size_t)i * 8);
        q[0] = o0; q[1] = o1;
    }
}

// ============================================================================
// TF32 GEMM: C[M,N] = A[M,K] @ W[N,K]^T + bias. A,W pre-rounded AND
// pair-permuted along k. 2-stage cp.async ring, k32 stages, coalesced.
// Fragment loads are LDS.64 (smem stride 40 == 8 mod 32: conflict-free).
// MODE 0: C row-major [M,N]. MODE 1: headed scatter to [B,H,T,HD], tf32 store
// in NATURAL order (attention consumes natural layout).
// ============================================================================
#define GEMM_STAGE_F (2 * 128 * 40)
#define GEMM_SMEM_BYTES (2 * GEMM_STAGE_F * 4)      // 81920 bytes

template <int MODE>
__global__ __launch_bounds__(256) void gemm_tf32(
    const float* __restrict__ A, const float* __restrict__ W,
    const float* __restrict__ bias, float* __restrict__ C,
    int M, int N, int K)
{
    extern __shared__ float sm[];

    const int tid  = threadIdx.x;
    const int m0   = blockIdx.y * 128;
    const int n0   = blockIdx.x * 128;
    const int warp = tid >> 5, lane = tid & 31;
    const int wm   = warp >> 1;
    const int wn   = warp & 1;
    const int gid  = lane >> 2;
    const int tig  = lane & 3;

    float acc[2][8][4];
#pragma unroll
    for (int i = 0; i < 2; i++)
#pragma unroll
        for (int j = 0; j < 8; j++)
#pragma unroll
            for (int r = 0; r < 4; r++) acc[i][j][r] = 0.f;

    const int row_ld = tid >> 3;
    const int col_ld = (tid & 7) * 4;
    const float* ga0 = A + (size_t)(m0 + row_ld) * K + col_ld;
    const float* gb0 = W + (size_t)(n0 + row_ld) * K + col_ld;

    auto issue = [&](int kt, int s) {
        float* Asf = sm + (size_t)s * GEMM_STAGE_F;
        float* Bsf = Asf + 128 * 40;
        const float* ga = ga0 + kt * 32;
        const float* gb = gb0 + kt * 32;
#pragma unroll
        for (int p = 0; p < 4; ++p) {
            uint32_t sa = (uint32_t)__cvta_generic_to_shared(Asf + (row_ld + p * 32) * 40 + col_ld);
            uint32_t sb = (uint32_t)__cvta_generic_to_shared(Bsf + (row_ld + p * 32) * 40 + col_ld);
            cp16(sa, ga + (size_t)p * 32 * K);
            cp16(sb, gb + (size_t)p * 32 * K);
        }
    };

    const int KT = K >> 5;
    issue(0, 0); cp_commit();

    for (int kt = 0; kt < KT; ++kt) {
        const int buf = kt & 1;
        cp_wait0();
        __syncthreads();
        if (kt + 1 < KT) { issue(kt + 1, buf ^ 1); cp_commit(); }

        const float* As = sm + (size_t)buf * GEMM_STAGE_F;
        const float* Bs = As + 128 * 40;

#pragma unroll
        for (int ks = 0; ks < 4; ++ks) {
            const int k = ks * 8;           // permuted block base; +2*tig = pair
            uint32_t af[2][4];
#pragma unroll
            for (int mf = 0; mf < 2; ++mf) {
                int r = wm * 32 + mf * 16;
                float2 p0 = *(const float2*)&As[(r + gid    ) * 40 + k + 2 * tig];
                float2 p1 = *(const float2*)&As[(r + gid + 8) * 40 + k + 2 * tig];
                af[mf][0] = __float_as_uint(p0.x);
                af[mf][1] = __float_as_uint(p1.x);
                af[mf][2] = __float_as_uint(p0.y);
                af[mf][3] = __float_as_uint(p1.y);
            }
            uint32_t bf[8][2];
#pragma unroll
            for (int nf = 0; nf < 8; ++nf) {
                int c = wn * 64 + nf * 8;
                float2 pb = *(const float2*)&Bs[(c + gid) * 40 + k + 2 * tig];
                bf[nf][0] = __float_as_uint(pb.x);
                bf[nf][1] = __float_as_uint(pb.y);
            }
#pragma unroll
            for (int mf = 0; mf < 2; ++mf)
#pragma unroll
                for (int nf = 0; nf < 8; ++nf)
                    mma8(acc[mf][nf], af[mf], bf[nf]);
        }
    }

#pragma unroll
    for (int mf = 0; mf < 2; ++mf) {
#pragma unroll
        for (int nf = 0; nf < 8; ++nf) {
            int col  = n0 + wn * 64 + nf * 8 + tig * 2;
            float b0 = bias[col], b1 = bias[col + 1];
            int row0 = m0 + wm * 32 + mf * 16 + gid;
            if (MODE == 0) {
                float2 v0 = make_float2(acc[mf][nf][0] + b0, acc[mf][nf][1] + b1);
                float2 v1 = make_float2(acc[mf][nf][2] + b0, acc[mf][nf][3] + b1);
                *(float2*)(C + (size_t)row0 * N + col)       = v0;
                *(float2*)(C + (size_t)(row0 + 8) * N + col) = v1;
            } else {
                float2 v0 = make_float2(to_tf32(acc[mf][nf][0] + b0), to_tf32(acc[mf][nf][1] + b1));
                float2 v1 = make_float2(to_tf32(acc[mf][nf][2] + b0), to_tf32(acc[mf][nf][3] + b1));
                int b  = row0 >> 11;
                int hh = col >> 6;
                size_t i0 = (((size_t)b * H_ + hh) * T_ + (row0 & 2047)) * HD_ + (col & 63);
                size_t i1 = (((size_t)b * H_ + hh) * T_ + ((row0 + 8) & 2047)) * HD_ + (col & 63);
                *(float2*)(C + i0) = v0;
                *(float2*)(C + i1) = v1;
            }
        }
    }
}

// ============================================================================
// Causal flash attention (unchanged from R10 except ctx is written in the
// pair-permuted k order consumed by the final GEMM).
// ============================================================================
#define AT_QS   0
#define AT_SS   (64 * 68)
#define AT_KS   (2 * 64 * 68)
#define AT_VS   (4 * 64 * 68)
#define AT_KSTG (64 * 68)
#define AT_VSTG (64 * 72)
#define ATTN_SMEM_F (4 * 64 * 68 + 2 * 64 * 72)
#define ATTN_SMEM_BYTES (ATTN_SMEM_F * 4)           // 106496 bytes

__device__ __forceinline__ int perm_col(int c) {
    int j = c & 7;
    return (c & ~7) + ((j < 4) ? (2 * j) : (2 * (j - 4) + 1));
}

__global__ __launch_bounds__(256) void attn_flash(
    const float* __restrict__ Q, const float* __restrict__ K,
    const float* __restrict__ V, float* __restrict__ ctx)
{
    extern __shared__ float sm[];
    float* Qs = sm + AT_QS;     // [64][68]
    float* Ss = sm + AT_SS;     // [64][68]
    float* Ks = sm + AT_KS;     // 2 x [64][68]
    float* Vs = sm + AT_VS;     // 2 x [64][72]
    __shared__ float mrow[64], lrow[64], frow[64];

    const int tid  = threadIdx.x;
    const int warp = tid >> 5, lane = tid & 31;
    const int gid  = lane >> 2, tig = lane & 3;
    const int wm   = warp >> 1;
    const int wn   = warp & 1;
    const int qt   = blockIdx.x;
    const int bh   = blockIdx.y;

    const float* Qg = Q + (size_t)bh * T_ * HD_ + (size_t)qt * 64 * HD_;
    const float* Kg = K + (size_t)bh * T_ * HD_;
    const float* Vg = V + (size_t)bh * T_ * HD_;

    {
#pragma unroll
        for (int i = 0; i < 4; ++i) {
            int f = tid + 256 * i;
            int r = f >> 4, c = (f & 15) * 4;
            *(float4*)(Qs + r * 68 + c) = *(const float4*)(Qg + (size_t)r * HD_ + c);
        }
    }
    if (tid < 64) { mrow[tid] = -1e30f; lrow[tid] = 0.f; }

    auto issue_kv = [&](int t, int s) {
        const float* Kt = Kg + (size_t)t * 64 * HD_;
        const float* Vt = Vg + (size_t)t * 64 * HD_;
        float* Kd = Ks + (size_t)s * AT_KSTG;
        float* Vd = Vs + (size_t)s * AT_VSTG;
#pragma unroll
        for (int i = 0; i < 4; ++i) {
            int f = tid + 256 * i;
            int r = f >> 4, c = (f & 15) * 4;
            cp16((uint32_t)__cvta_generic_to_shared(Kd + r * 68 + c), Kt + (size_t)r * HD_ + c);
            cp16((uint32_t)__cvta_generic_to_shared(Vd + r * 72 + c), Vt + (size_t)r * HD_ + c);
        }
    };

    float oacc[4][4];
#pragma unroll
    for (int i = 0; i < 4; i++)
#pragma unroll
        for (int j = 0; j < 4; j++) oacc[i][j] = 0.f;

    const int nkv = qt + 1;
    issue_kv(0, 0); cp_commit();

    for (int t = 0; t < nkv; ++t) {
        const int buf = t & 1;
        cp_wait0();
        __syncthreads();
        if (t + 1 < nkv) { issue_kv(t + 1, buf ^ 1); cp_commit(); }

        const float* Kb = Ks + (size_t)buf * AT_KSTG;
        const float* Vb = Vs + (size_t)buf * AT_VSTG;

        float sacc[4][4];
#pragma unroll
        for (int i = 0; i < 4; i++)
#pragma unroll
            for (int j = 0; j < 4; j++) sacc[i][j] = 0.f;

#pragma unroll
        for (int ks = 0; ks < 8; ++ks) {
            const int k = ks * 8;
            uint32_t af[4];
            int r = wm * 16;
            af[0] = __float_as_uint(Qs[(r + gid    ) * 68 + k + tig    ]);
            af[1] = __float_as_uint(Qs[(r + gid + 8) * 68 + k + tig    ]);
            af[2] = __float_as_uint(Qs[(r + gid    ) * 68 + k + tig + 4]);
            af[3] = __float_as_uint(Qs[(r + gid + 8) * 68 + k + tig + 4]);
#pragma unroll
            for (int nf = 0; nf < 4; ++nf) {
                int c = wn * 32 + nf * 8;
                uint32_t bf[2];
                bf[0] = __float_as_uint(Kb[(c + gid) * 68 + k + tig    ]);
                bf[1] = __float_as_uint(Kb[(c + gid) * 68 + k + tig + 4]);
                mma8(sacc[nf], af, bf);
            }
        }
#pragma unroll
        for (int nf = 0; nf < 4; ++nf) {
            int col = wn * 32 + nf * 8 + tig * 2;
            int row = wm * 16 + gid;
            Ss[(row    ) * 68 + col    ] = sacc[nf][0];
            Ss[(row    ) * 68 + col + 1] = sacc[nf][1];
            Ss[(row + 8) * 68 + col    ] = sacc[nf][2];
            Ss[(row + 8) * 68 + col + 1] = sacc[nf][3];
        }
        __syncthreads();

        {
            const int r = tid >> 2, q = tid & 3;
            float vb[16];
            float mx = -1e30f;
            if (t == qt) {
                const int grow = qt * 64 + (tid >> 2);
#pragma unroll
                for (int j = 0; j < 16; ++j) {
                    int c  = q + 4 * j;
                    float x = Ss[r * 68 + c] * SCALE_;
                    if (t * 64 + c > grow) x = -1e30f;
                    vb[j] = x;
                    mx = fmaxf(mx, x);
                }
            } else {
#pragma unroll
                for (int j = 0; j < 16; ++j) {
                    float x = Ss[r * 68 + q + 4 * j] * SCALE_;
                    vb[j] = x;
                    mx = fmaxf(mx, x);
                }
            }
            mx = fmaxf(mx, __shfl_xor_sync(0xffffffffu, mx, 1));
            mx = fmaxf(mx, __shfl_xor_sync(0xffffffffu, mx, 2));
            float mold = mrow[r];
            float mnew = fmaxf(mold, mx);
            float s = 0.f;
#pragma unroll
            for (int j = 0; j < 16; ++j) {
                float p = __expf(vb[j] - mnew);
                s += p;
                Ss[r * 68 + q + 4 * j] = to_tf32(p);
            }
            s += __shfl_xor_sync(0xffffffffu, s, 1);
            s += __shfl_xor_sync(0xffffffffu, s, 2);
            if (q == 0) {
                float f = __expf(mold - mnew);
                frow[r] = f;
                mrow[r] = mnew;
                lrow[r] = lrow[r] * f + s;
            }
        }
        __syncthreads();

        {
            float f0 = frow[wm * 16 + gid];
            float f8 = frow[wm * 16 + gid + 8];
#pragma unroll
            for (int nf = 0; nf < 4; ++nf) {
                oacc[nf][0] *= f0; oacc[nf][1] *= f0;
                oacc[nf][2] *= f8; oacc[nf][3] *= f8;
            }
        }
#pragma unroll
        for (int ks = 0; ks < 8; ++ks) {
            const int k = ks * 8;
            uint32_t af[4];
            int r = wm * 16;
            af[0] = __float_as_uint(Ss[(r + gid    ) * 68 + k + tig    ]);
            af[1] = __float_as_uint(Ss[(r + gid + 8) * 68 + k + tig    ]);
            af[2] = __float_as_uint(Ss[(r + gid    ) * 68 + k + tig + 4]);
            af[3] = __float_as_uint(Ss[(r + gid + 8) * 68 + k + tig + 4]);
#pragma unroll
            for (int nf = 0; nf < 4; ++nf) {
                int c = wn * 32 + nf * 8;
                uint32_t bf[2];
                bf[0] = __float_as_uint(Vb[(k + tig    ) * 72 + c + gid]);
                bf[1] = __float_as_uint(Vb[(k + tig + 4) * 72 + c + gid]);
                mma8(oacc[nf], af, bf);
            }
        }
    }

    // ---- write ctx [B,T,D]: tf32-rounded, PAIR-PERMUTED along D ----
    {
        int r0 = wm * 16 + gid;
        float il0 = 1.f / lrow[r0];
        float il8 = 1.f / lrow[r0 + 8];
        int b = bh >> 5, h = bh & 31;
        size_t base = ((size_t)b * T_ + (size_t)qt * 64) * D_ + h * 64;
        float* c0p = ctx + base + (size_t)r0 * D_;
        float* c8p = ctx + base + (size_t)(r0 + 8) * D_;
#pragma unroll
        for (int nf = 0; nf < 4; ++nf) {
            int col = wn * 32 + nf * 8 + tig * 2;
            int pc0 = perm_col(col), pc1 = perm_col(col + 1);
            c0p[pc0] = to_tf32(oacc[nf][0] * il0);
            c0p[pc1] = to_tf32(oacc[nf][1] * il0);
            c8p[pc0] = to_tf32(oacc[nf][2] * il8);
            c8p[pc1] = to_tf32(oacc[nf][3] * il8);
        }
    }
}

// ============================================================================
extern "C" void kernel_launch(void* const* d_in, const int* in_sizes, int n_in,
                              void* d_out, int out_size)
{
    (void)in_sizes; (void)n_in; (void)out_size;
    const float* X  = (const float*)d_in[0];
    const float* Wq = (const float*)d_in[1];
    const float* bq = (const float*)d_in[2];
    const float* Wk = (const float*)d_in[3];
    const float* bk = (const float*)d_in[4];
    const float* Wv = (const float*)d_in[5];
    const float* bv = (const float*)d_in[6];
    const float* Wo = (const float*)d_in[7];
    const float* bo = (const float*)d_in[8];
    float* out = (float*)d_out;

    float *x, *wq, *wk, *wv, *wo, *q, *k, *v, *ctx;
    cudaGetSymbolAddress((void**)&x,   g_x);
    cudaGetSymbolAddress((void**)&wq,  g_wq);
    cudaGetSymbolAddress((void**)&wk,  g_wk);
    cudaGetSymbolAddress((void**)&wv,  g_wv);
    cudaGetSymbolAddress((void**)&wo,  g_wo);
    cudaGetSymbolAddress((void**)&q,   g_q);
    cudaGetSymbolAddress((void**)&k,   g_k);
    cudaGetSymbolAddress((void**)&v,   g_v);
    cudaGetSymbolAddress((void**)&ctx, g_ctx);

    cudaFuncSetAttribute(gemm_tf32<0>, cudaFuncAttributeMaxDynamicSharedMemorySize, GEMM_SMEM_BYTES);
    cudaFuncSetAttribute(gemm_tf32<1>, cudaFuncAttributeMaxDynamicSharedMemorySize, GEMM_SMEM_BYTES);
    cudaFuncSetAttribute(attn_flash,   cudaFuncAttributeMaxDynamicSharedMemorySize, ATTN_SMEM_BYTES);

    // pre-round + pair-permute activations and weights
    const int nxb = B_ * T_ * D_ / 8;   // 1048576 k-blocks
    const int nwb = D_ * D_ / 8;        // 524288
    round_perm_kernel<<<nxb / 256, 256>>>(X,  x,  nxb);
    round_perm_kernel<<<nwb / 256, 256>>>(Wq, wq, nwb);
    round_perm_kernel<<<nwb / 256, 256>>>(Wk, wk, nwb);
    round_perm_kernel<<<nwb / 256, 256>>>(Wv, wv, nwb);
    round_perm_kernel<<<nwb / 256, 256>>>(Wo, wo, nwb);

    const int M = B_ * T_;   // 4096
    const int N = D_;        // 2048
    const int K = D_;        // 2048
    dim3 gg(N / 128, M / 128);   // 16 x 32

    gemm_tf32<1><<<gg, 256, GEMM_SMEM_BYTES>>>(x, wq, bq, q, M, N, K);
    gemm_tf32<1><<<gg, 256, GEMM_SMEM_BYTES>>>(x, wk, bk, k, M, N, K);
    gemm_tf32<1><<<gg, 256, GEMM_SMEM_BYTES>>>(x, wv, bv, v, M, N, K);

    attn_flash<<<dim3(T_ / 64, B_ * H_), 256, ATTN_SMEM_BYTES>>>(q, k, v, ctx);

    gemm_tf32<0><<<gg, 256, GEMM_SMEM_BYTES>>>(ctx, wo, bo, out, M, N, K);
}

// round 13
// speedup vs baseline: 1.8317x; 1.8317x over previous
#include <cuda_runtime.h>
#include <cuda_fp16.h>
#include <cstdint>

#define B_  2
#define T_  2048
#define D_  2048
#define H_  32
#define HD_ 64
#define SCALE_ 0.125f   // 1/sqrt(64)

// ---------------- scratch (device globals: allocation-free) ----------------
__device__ __half g_x [(size_t)B_ * T_ * D_];
__device__ __half g_wq[(size_t)D_ * D_];
__device__ __half g_wk[(size_t)D_ * D_];
__device__ __half g_wv[(size_t)D_ * D_];
__device__ __half g_wo[(size_t)D_ * D_];
__device__ __half g_q [(size_t)B_ * H_ * T_ * HD_];
__device__ __half g_k [(size_t)B_ * H_ * T_ * HD_];
__device__ __half g_v [(size_t)B_ * H_ * T_ * HD_];
__device__ __half g_ctx[(size_t)B_ * T_ * D_];

// ---------------- helpers ----------------
__device__ __forceinline__ void mma16(float* c, const uint32_t* a, const uint32_t* b) {
    asm volatile(
        "mma.sync.aligned.m16n8k16.row.col.f32.f16.f16.f32 "
        "{%0,%1,%2,%3},{%4,%5,%6,%7},{%8,%9},{%0,%1,%2,%3};\n"
        : "+f"(c[0]), "+f"(c[1]), "+f"(c[2]), "+f"(c[3])
        : "r"(a[0]), "r"(a[1]), "r"(a[2]), "r"(a[3]), "r"(b[0]), "r"(b[1]));
}

__device__ __forceinline__ void cp16(uint32_t saddr, const void* g) {
    asm volatile("cp.async.cg.shared.global [%0], [%1], 16;\n"
                 :: "r"(saddr), "l"(g) : "memory");
}
__device__ __forceinline__ void cp_commit() {
    asm volatile("cp.async.commit_group;\n" ::: "memory");
}
__device__ __forceinline__ void cp_wait0() {
    asm volatile("cp.async.wait_group 0;\n" ::: "memory");
}

__device__ __forceinline__ void ldsm_x2_trans(uint32_t& b0, uint32_t& b1, uint32_t addr) {
    asm volatile("ldmatrix.sync.aligned.m8n8.x2.trans.shared.b16 {%0,%1}, [%2];"
                 : "=r"(b0), "=r"(b1) : "r"(addr));
}

// ============================================================================
// fp32 -> fp16 convert (vectorized)
// ============================================================================
__global__ __launch_bounds__(256) void to_half_kernel(
    const float4* __restrict__ in, uint2* __restrict__ out, int n4)
{
    int i = blockIdx.x * 256 + threadIdx.x;
    if (i < n4) {
        float4 v = in[i];
        __half2 h0 = __floats2half2_rn(v.x, v.y);
        __half2 h1 = __floats2half2_rn(v.z, v.w);
        out[i] = make_uint2(*(uint32_t*)&h0, *(uint32_t*)&h1);
    }
}

// ============================================================================
// FP16 GEMM: C[M,N] = A[M,K] @ W[N,K]^T + bias, A/W fp16, fp32 accum.
// 2-stage cp.async ring, k64 stages (128B rows), coalesced (4 lines/instr).
// smem rows stride 72 halves (36 words == 4 mod 32: conflict-free half2 frags).
// Block tile 128x128, 8 warps (4x2), warp tile 32x64, mma m16n8k16.
// MODE 0: C fp32 row-major [M,N]. MODE 1: scatter to [B,H,T,HD] as fp16.
// ============================================================================
#define GEMM_STAGE_H (2 * 128 * 72)                  // halves per stage (A+B)
#define GEMM_SMEM_BYTES (2 * GEMM_STAGE_H * 2)       // 73728 bytes

template <int MODE>
__global__ __launch_bounds__(256) void gemm_f16(
    const __half* __restrict__ A, const __half* __restrict__ W,
    const float* __restrict__ bias, void* __restrict__ Cv,
    int M, int N, int K)
{
    extern __shared__ __half smh[];

    const int tid  = threadIdx.x;
    const int m0   = blockIdx.y * 128;
    const int n0   = blockIdx.x * 128;
    const int warp = tid >> 5, lane = tid & 31;
    const int wm   = warp >> 1;       // 0..3
    const int wn   = warp & 1;        // 0..1
    const int gid  = lane >> 2;       // 0..7
    const int tig  = lane & 3;        // 0..3

    float acc[2][8][4];
#pragma unroll
    for (int i = 0; i < 2; i++)
#pragma unroll
        for (int j = 0; j < 8; j++)
#pragma unroll
            for (int r = 0; r < 4; r++) acc[i][j][r] = 0.f;

    // stage = 128 rows x 64 halves (128 bytes); 8 chunks of 16B per row
    auto issue = [&](int kt, int s) {
        __half* Ah = smh + (size_t)s * GEMM_STAGE_H;
        __half* Bh = Ah + 128 * 72;
        const __half* ga = A + (size_t)m0 * K + (size_t)kt * 64;
        const __half* gb = W + (size_t)n0 * K + (size_t)kt * 64;
#pragma unroll
        for (int i = 0; i < 4; ++i) {
            int f  = tid + 256 * i;          // 0..1023
            int r  = f >> 3;                 // 0..127
            int ch = (f & 7);                // 16B chunk
            cp16((uint32_t)__cvta_generic_to_shared(Ah + r * 72 + ch * 8),
                 ga + (size_t)r * K + ch * 8);
            cp16((uint32_t)__cvta_generic_to_shared(Bh + r * 72 + ch * 8),
                 gb + (size_t)r * K + ch * 8);
        }
    };

    const int KT = K >> 6;   // 64-wide stages (32 total)
    issue(0, 0); cp_commit();

    for (int kt = 0; kt < KT; ++kt) {
        const int buf = kt & 1;
        cp_wait0();
        __syncthreads();
        if (kt + 1 < KT) { issue(kt + 1, buf ^ 1); cp_commit(); }

        const __half* As = smh + (size_t)buf * GEMM_STAGE_H;
        const __half* Bs = As + 128 * 72;

#pragma unroll
        for (int ks = 0; ks < 4; ++ks) {
            const int k = ks * 16;
            uint32_t af[2][4];
#pragma unroll
            for (int mf = 0; mf < 2; ++mf) {
                int rr = wm * 32 + mf * 16;
                af[mf][0] = *(const uint32_t*)&As[(rr + gid    ) * 72 + k + 2 * tig    ];
                af[mf][1] = *(const uint32_t*)&As[(rr + gid + 8) * 72 + k + 2 * tig    ];
                af[mf][2] = *(const uint32_t*)&As[(rr + gid    ) * 72 + k + 2 * tig + 8];
                af[mf][3] = *(const uint32_t*)&As[(rr + gid + 8) * 72 + k + 2 * tig + 8];
            }
            uint32_t bf[8][2];
#pragma unroll
            for (int nf = 0; nf < 8; ++nf) {
                int cc = wn * 64 + nf * 8;
                bf[nf][0] = *(const uint32_t*)&Bs[(cc + gid) * 72 + k + 2 * tig    ];
                bf[nf][1] = *(const uint32_t*)&Bs[(cc + gid) * 72 + k + 2 * tig + 8];
            }
#pragma unroll
            for (int mf = 0; mf < 2; ++mf)
#pragma unroll
                for (int nf = 0; nf < 8; ++nf)
                    mma16(acc[mf][nf], af[mf], bf[nf]);
        }
    }

    // epilogue
#pragma unroll
    for (int mf = 0; mf < 2; ++mf) {
#pragma unroll
        for (int nf = 0; nf < 8; ++nf) {
            int col  = n0 + wn * 64 + nf * 8 + tig * 2;
            float b0 = bias[col], b1 = bias[col + 1];
            int row0 = m0 + wm * 32 + mf * 16 + gid;
            if (MODE == 0) {
                float* C = (float*)Cv;
                float2 v0 = make_float2(acc[mf][nf][0] + b0, acc[mf][nf][1] + b1);
                float2 v1 = make_float2(acc[mf][nf][2] + b0, acc[mf][nf][3] + b1);
                *(float2*)(C + (size_t)row0 * N + col)       = v0;
                *(float2*)(C + (size_t)(row0 + 8) * N + col) = v1;
            } else {
                __half* C = (__half*)Cv;
                __half2 v0 = __floats2half2_rn(acc[mf][nf][0] + b0, acc[mf][nf][1] + b1);
                __half2 v1 = __floats2half2_rn(acc[mf][nf][2] + b0, acc[mf][nf][3] + b1);
                int b  = row0 >> 11;
                int hh = col >> 6;
                size_t i0 = (((size_t)b * H_ + hh) * T_ + (row0 & 2047)) * HD_ + (col & 63);
                size_t i1 = (((size_t)b * H_ + hh) * T_ + ((row0 + 8) & 2047)) * HD_ + (col & 63);
                *(__half2*)(C + i0) = v0;
                *(__half2*)(C + i1) = v1;
            }
        }
    }
}

// ============================================================================
// Causal flash attention, fp16 mma m16n8k16, fp32 softmax/accum.
// Br=64, Bc=64, HD=64, 8 warps (4 wm x 2 wn). cp.async double-buffered K/V.
// V consumed straight from [kv][hd] via ldmatrix.x2.trans.
// smem (bytes): Ss f32 64x68 @0 | Qs h 64x72 | Ps h 64x72 | Ks h 2x64x72 |
//               Vs h 2x64x72.  Total 72704.
// ============================================================================
#define AB_SS 0
#define AB_QS 17408
#define AB_PS (AB_QS + 9216)
#define AB_KS (AB_PS + 9216)
#define AB_VS (AB_KS + 2 * 9216)
#define ATTN_SMEM_BYTES (AB_VS + 2 * 9216)   // 72704

__global__ __launch_bounds__(256) void attn_flash(
    const __half* __restrict__ Q, const __half* __restrict__ K,
    const __half* __restrict__ V, __half* __restrict__ ctx)
{
    extern __shared__ char smc[];
    float*  Ss = (float*)(smc + AB_SS);          // [64][68]
    __half* Qs = (__half*)(smc + AB_QS);         // [64][72]
    __half* Ps = (__half*)(smc + AB_PS);         // [64][72]
    __half* Ks = (__half*)(smc + AB_KS);         // 2 x [64][72]
    __half* Vs = (__half*)(smc + AB_VS);         // 2 x [64][72]
    __shared__ float mrow[64], lrow[64], frow[64];

    const int tid  = threadIdx.x;
    const int warp = tid >> 5, lane = tid & 31;
    const int gid  = lane >> 2, tig = lane & 3;
    const int wm   = warp >> 1;
    const int wn   = warp & 1;
    const int qt   = blockIdx.x;
    const int bh   = blockIdx.y;

    const __half* Qg = Q + (size_t)bh * T_ * HD_ + (size_t)qt * 64 * HD_;
    const __half* Kg = K + (size_t)bh * T_ * HD_;
    const __half* Vg = V + (size_t)bh * T_ * HD_;

    // load Q tile: 64 rows x 64 halves, 16B chunks
    {
#pragma unroll
        for (int i = 0; i < 2; ++i) {
            int f = tid + 256 * i;           // 0..511
            int r = f >> 3, ch = f & 7;
            *(uint4*)(Qs + r * 72 + ch * 8) = *(const uint4*)(Qg + (size_t)r * HD_ + ch * 8);
        }
    }
    if (tid < 64) { mrow[tid] = -1e30f; lrow[tid] = 0.f; }

    auto issue_kv = [&](int t, int s) {
        const __half* Kt = Kg + (size_t)t * 64 * HD_;
        const __half* Vt = Vg + (size_t)t * 64 * HD_;
        __half* Kd = Ks + (size_t)s * (64 * 72);
        __half* Vd = Vs + (size_t)s * (64 * 72);
#pragma unroll
        for (int i = 0; i < 2; ++i) {
            int f = tid + 256 * i;
            int r = f >> 3, ch = f & 7;
            cp16((uint32_t)__cvta_generic_to_shared(Kd + r * 72 + ch * 8),
                 Kt + (size_t)r * HD_ + ch * 8);
            cp16((uint32_t)__cvta_generic_to_shared(Vd + r * 72 + ch * 8),
                 Vt + (size_t)r * HD_ + ch * 8);
        }
    };

    float oacc[4][4];
#pragma unroll
    for (int i = 0; i < 4; i++)
#pragma unroll
        for (int j = 0; j < 4; j++) oacc[i][j] = 0.f;

    const int nkv = qt + 1;
    issue_kv(0, 0); cp_commit();

    for (int t = 0; t < nkv; ++t) {
        const int buf = t & 1;
        cp_wait0();
        __syncthreads();
        if (t + 1 < nkv) { issue_kv(t + 1, buf ^ 1); cp_commit(); }

        const __half* Kb = Ks + (size_t)buf * (64 * 72);
        const __half* Vb = Vs + (size_t)buf * (64 * 72);

        // ---- S = Q @ K^T : warp rows [wm*16,+16), kv cols [wn*32,+32) ----
        float sacc[4][4];
#pragma unroll
        for (int i = 0; i < 4; i++)
#pragma unroll
            for (int j = 0; j < 4; j++) sacc[i][j] = 0.f;

#pragma unroll
        for (int ks = 0; ks < 4; ++ks) {
            const int k = ks * 16;
            uint32_t af[4];
            int rr = wm * 16;
            af[0] = *(const uint32_t*)&Qs[(rr + gid    ) * 72 + k + 2 * tig    ];
            af[1] = *(const uint32_t*)&Qs[(rr + gid + 8) * 72 + k + 2 * tig    ];
            af[2] = *(const uint32_t*)&Qs[(rr + gid    ) * 72 + k + 2 * tig + 8];
            af[3] = *(const uint32_t*)&Qs[(rr + gid + 8) * 72 + k + 2 * tig + 8];
#pragma unroll
            for (int nf = 0; nf < 4; ++nf) {
                int cc = wn * 32 + nf * 8;
                uint32_t bf[2];
                bf[0] = *(const uint32_t*)&Kb[(cc + gid) * 72 + k + 2 * tig    ];
                bf[1] = *(const uint32_t*)&Kb[(cc + gid) * 72 + k + 2 * tig + 8];
                mma16(sacc[nf], af, bf);
            }
        }
#pragma unroll
        for (int nf = 0; nf < 4; ++nf) {
            int col = wn * 32 + nf * 8 + tig * 2;
            int row = wm * 16 + gid;
            Ss[(row    ) * 68 + col    ] = sacc[nf][0];
            Ss[(row    ) * 68 + col + 1] = sacc[nf][1];
            Ss[(row + 8) * 68 + col    ] = sacc[nf][2];
            Ss[(row + 8) * 68 + col + 1] = sacc[nf][3];
        }
        __syncthreads();

        // ---- online softmax: 4 threads/row, cols c = q + 4j; P -> fp16 ----
        {
            const int r = tid >> 2, q = tid & 3;
            float vb[16];
            float mx = -1e30f;
            if (t == qt) {
                const int grow = qt * 64 + r;
#pragma unroll
                for (int j = 0; j < 16; ++j) {
                    int c  = q + 4 * j;
                    float x = Ss[r * 68 + c] * SCALE_;
                    if (t * 64 + c > grow) x = -1e30f;
                    vb[j] = x;
                    mx = fmaxf(mx, x);
                }
            } else {
#pragma unroll
                for (int j = 0; j < 16; ++j) {
                    float x = Ss[r * 68 + q + 4 * j] * SCALE_;
                    vb[j] = x;
                    mx = fmaxf(mx, x);
                }
            }
            mx = fmaxf(mx, __shfl_xor_sync(0xffffffffu, mx, 1));
            mx = fmaxf(mx, __shfl_xor_sync(0xffffffffu, mx, 2));
            float mold = mrow[r];
            float mnew = fmaxf(mold, mx);
            float s = 0.f;
#pragma unroll
            for (int j = 0; j < 16; ++j) {
                float p = __expf(vb[j] - mnew);
                s += p;
                Ps[r * 72 + q + 4 * j] = __float2half_rn(p);
            }
            s += __shfl_xor_sync(0xffffffffu, s, 1);
            s += __shfl_xor_sync(0xffffffffu, s, 2);
            if (q == 0) {
                float f = __expf(mold - mnew);
                frow[r] = f;
                mrow[r] = mnew;
                lrow[r] = lrow[r] * f + s;
            }
        }
        __syncthreads();

        // ---- rescale O, then O += P @ V (V via ldmatrix.trans) ----
        {
            float f0 = frow[wm * 16 + gid];
            float f8 = frow[wm * 16 + gid + 8];
#pragma unroll
            for (int nf = 0; nf < 4; ++nf) {
                oacc[nf][0] *= f0; oacc[nf][1] *= f0;
                oacc[nf][2] *= f8; oacc[nf][3] *= f8;
            }
        }
        const int l16 = lane & 15;
#pragma unroll
        for (int ks = 0; ks < 4; ++ks) {
            const int k = ks * 16;
            uint32_t af[4];
            int rr = wm * 16;
            af[0] = *(const uint32_t*)&Ps[(rr + gid    ) * 72 + k + 2 * tig    ];
            af[1] = *(const uint32_t*)&Ps[(rr + gid + 8) * 72 + k + 2 * tig    ];
            af[2] = *(const uint32_t*)&Ps[(rr + gid    ) * 72 + k + 2 * tig + 8];
            af[3] = *(const uint32_t*)&Ps[(rr + gid + 8) * 72 + k + 2 * tig + 8];
#pragma unroll
            for (int nf = 0; nf < 4; ++nf) {
                int cc = wn * 32 + nf * 8;
                uint32_t b0, b1;
                uint32_t vaddr = (uint32_t)__cvta_generic_to_shared(
                    Vb + (size_t)(k + l16) * 72 + cc);
                ldsm_x2_trans(b0, b1, vaddr);
                uint32_t bf[2] = { b0, b1 };
                mma16(oacc[nf], af, bf);
            }
        }
    }

    // ---- write ctx [B,T,D] fp16 ----
    {
        int r0 = wm * 16 + gid;
        float il0 = 1.f / lrow[r0];
        float il8 = 1.f / lrow[r0 + 8];
        int b = bh >> 5, h = bh & 31;
        size_t base = ((size_t)b * T_ + (size_t)qt * 64) * D_ + h * 64;
#pragma unroll
        for (int nf = 0; nf < 4; ++nf) {
            int col = wn * 32 + nf * 8 + tig * 2;
            __half2 v0 = __floats2half2_rn(oacc[nf][0] * il0, oacc[nf][1] * il0);
            __half2 v1 = __floats2half2_rn(oacc[nf][2] * il8, oacc[nf][3] * il8);
            *(__half2*)(ctx + base + (size_t)r0 * D_ + col)       = v0;
            *(__half2*)(ctx + base + (size_t)(r0 + 8) * D_ + col) = v1;
        }
    }
}

// ============================================================================
extern "C" void kernel_launch(void* const* d_in, const int* in_sizes, int n_in,
                              void* d_out, int out_size)
{
    (void)in_sizes; (void)n_in; (void)out_size;
    const float* X  = (const float*)d_in[0];
    const float* Wq = (const float*)d_in[1];
    const float* bq = (const float*)d_in[2];
    const float* Wk = (const float*)d_in[3];
    const float* bk = (const float*)d_in[4];
    const float* Wv = (const float*)d_in[5];
    const float* bv = (const float*)d_in[6];
    const float* Wo = (const float*)d_in[7];
    const float* bo = (const float*)d_in[8];
    float* out = (float*)d_out;

    __half *x, *wq, *wk, *wv, *wo, *q, *k, *v, *ctx;
    cudaGetSymbolAddress((void**)&x,   g_x);
    cudaGetSymbolAddress((void**)&wq,  g_wq);
    cudaGetSymbolAddress((void**)&wk,  g_wk);
    cudaGetSymbolAddress((void**)&wv,  g_wv);
    cudaGetSymbolAddress((void**)&wo,  g_wo);
    cudaGetSymbolAddress((void**)&q,   g_q);
    cudaGetSymbolAddress((void**)&k,   g_k);
    cudaGetSymbolAddress((void**)&v,   g_v);
    cudaGetSymbolAddress((void**)&ctx, g_ctx);

    cudaFuncSetAttribute(gemm_f16<0>, cudaFuncAttributeMaxDynamicSharedMemorySize, GEMM_SMEM_BYTES);
    cudaFuncSetAttribute(gemm_f16<1>, cudaFuncAttributeMaxDynamicSharedMemorySize, GEMM_SMEM_BYTES);
    cudaFuncSetAttribute(attn_flash,  cudaFuncAttributeMaxDynamicSharedMemorySize, ATTN_SMEM_BYTES);

    // convert activations + weights to fp16
    const int nx4 = B_ * T_ * D_ / 4;
    const int nw4 = D_ * D_ / 4;
    to_half_kernel<<<nx4 / 256, 256>>>((const float4*)X,  (uint2*)x,  nx4);
    to_half_kernel<<<nw4 / 256, 256>>>((const float4*)Wq, (uint2*)wq, nw4);
    to_half_kernel<<<nw4 / 256, 256>>>((const float4*)Wk, (uint2*)wk, nw4);
    to_half_kernel<<<nw4 / 256, 256>>>((const float4*)Wv, (uint2*)wv, nw4);
    to_half_kernel<<<nw4 / 256, 256>>>((const float4*)Wo, (uint2*)wo, nw4);

    const int M = B_ * T_;   // 4096
    const int N = D_;        // 2048
    const int K = D_;        // 2048
    dim3 gg(N / 128, M / 128);   // 16 x 32

    gemm_f16<1><<<gg, 256, GEMM_SMEM_BYTES>>>(x, wq, bq, q, M, N, K);
    gemm_f16<1><<<gg, 256, GEMM_SMEM_BYTES>>>(x, wk, bk, k, M, N, K);
    gemm_f16<1><<<gg, 256, GEMM_SMEM_BYTES>>>(x, wv, bv, v, M, N, K);

    attn_flash<<<dim3(T_ / 64, B_ * H_), 256, ATTN_SMEM_BYTES>>>(q, k, v, ctx);

    gemm_f16<0><<<gg, 256, GEMM_SMEM_BYTES>>>(ctx, wo, bo, out, M, N, K);
}

// round 14
// speedup vs baseline: 1.9988x; 1.0912x over previous
#include <cuda_runtime.h>
#include <cuda_fp16.h>
#include <cstdint>

#define B_  2
#define T_  2048
#define D_  2048
#define H_  32
#define HD_ 64
#define SCALE_ 0.125f   // 1/sqrt(64)

// ---------------- scratch (device globals: allocation-free) ----------------
__device__ __half g_x [(size_t)B_ * T_ * D_];
__device__ __half g_wq[(size_t)D_ * D_];
__device__ __half g_wk[(size_t)D_ * D_];
__device__ __half g_wv[(size_t)D_ * D_];
__device__ __half g_wo[(size_t)D_ * D_];
__device__ __half g_q [(size_t)B_ * H_ * T_ * HD_];
__device__ __half g_k [(size_t)B_ * H_ * T_ * HD_];
__device__ __half g_v [(size_t)B_ * H_ * T_ * HD_];
__device__ __half g_ctx[(size_t)B_ * T_ * D_];

// ---------------- helpers ----------------
__device__ __forceinline__ void mma16(float* c, const uint32_t* a, const uint32_t* b) {
    asm volatile(
        "mma.sync.aligned.m16n8k16.row.col.f32.f16.f16.f32 "
        "{%0,%1,%2,%3},{%4,%5,%6,%7},{%8,%9},{%0,%1,%2,%3};\n"
        : "+f"(c[0]), "+f"(c[1]), "+f"(c[2]), "+f"(c[3])
        : "r"(a[0]), "r"(a[1]), "r"(a[2]), "r"(a[3]), "r"(b[0]), "r"(b[1]));
}

__device__ __forceinline__ void cp16(uint32_t saddr, const void* g) {
    asm volatile("cp.async.cg.shared.global [%0], [%1], 16;\n"
                 :: "r"(saddr), "l"(g) : "memory");
}
__device__ __forceinline__ void cp_commit() {
    asm volatile("cp.async.commit_group;\n" ::: "memory");
}
__device__ __forceinline__ void cp_wait0() {
    asm volatile("cp.async.wait_group 0;\n" ::: "memory");
}

__device__ __forceinline__ void ldsm_x4_trans(uint32_t& r0, uint32_t& r1,
                                              uint32_t& r2, uint32_t& r3, uint32_t addr) {
    asm volatile("ldmatrix.sync.aligned.m8n8.x4.trans.shared.b16 {%0,%1,%2,%3}, [%4];"
                 : "=r"(r0), "=r"(r1), "=r"(r2), "=r"(r3) : "r"(addr));
}

__device__ __forceinline__ uint32_t h2pack(float a, float b) {
    __half2 h = __floats2half2_rn(a, b);
    return *(uint32_t*)&h;
}

// ============================================================================
// fp32 -> fp16 convert (vectorized)
// ============================================================================
__global__ __launch_bounds__(256) void to_half_kernel(
    const float4* __restrict__ in, uint2* __restrict__ out, int n4)
{
    int i = blockIdx.x * 256 + threadIdx.x;
    if (i < n4) {
        float4 v = in[i];
        __half2 h0 = __floats2half2_rn(v.x, v.y);
        __half2 h1 = __floats2half2_rn(v.z, v.w);
        out[i] = make_uint2(*(uint32_t*)&h0, *(uint32_t*)&h1);
    }
}

// ============================================================================
// FP16 GEMM (unchanged from R13): 2-stage cp.async ring, k64 stages,
// coalesced; stride 72 halves; block 128x128, 8 warps (4x2), mma m16n8k16.
// ============================================================================
#define GEMM_STAGE_H (2 * 128 * 72)
#define GEMM_SMEM_BYTES (2 * GEMM_STAGE_H * 2)       // 73728 bytes

template <int MODE>
__global__ __launch_bounds__(256) void gemm_f16(
    const __half* __restrict__ A, const __half* __restrict__ W,
    const float* __restrict__ bias, void* __restrict__ Cv,
    int M, int N, int K)
{
    extern __shared__ __half smh[];

    const int tid  = threadIdx.x;
    const int m0   = blockIdx.y * 128;
    const int n0   = blockIdx.x * 128;
    const int warp = tid >> 5, lane = tid & 31;
    const int wm   = warp >> 1;
    const int wn   = warp & 1;
    const int gid  = lane >> 2;
    const int tig  = lane & 3;

    float acc[2][8][4];
#pragma unroll
    for (int i = 0; i < 2; i++)
#pragma unroll
        for (int j = 0; j < 8; j++)
#pragma unroll
            for (int r = 0; r < 4; r++) acc[i][j][r] = 0.f;

    auto issue = [&](int kt, int s) {
        __half* Ah = smh + (size_t)s * GEMM_STAGE_H;
        __half* Bh = Ah + 128 * 72;
        const __half* ga = A + (size_t)m0 * K + (size_t)kt * 64;
        const __half* gb = W + (size_t)n0 * K + (size_t)kt * 64;
#pragma unroll
        for (int i = 0; i < 4; ++i) {
            int f  = tid + 256 * i;
            int r  = f >> 3;
            int ch = (f & 7);
            cp16((uint32_t)__cvta_generic_to_shared(Ah + r * 72 + ch * 8),
                 ga + (size_t)r * K + ch * 8);
            cp16((uint32_t)__cvta_generic_to_shared(Bh + r * 72 + ch * 8),
                 gb + (size_t)r * K + ch * 8);
        }
    };

    const int KT = K >> 6;
    issue(0, 0); cp_commit();

    for (int kt = 0; kt < KT; ++kt) {
        const int buf = kt & 1;
        cp_wait0();
        __syncthreads();
        if (kt + 1 < KT) { issue(kt + 1, buf ^ 1); cp_commit(); }

        const __half* As = smh + (size_t)buf * GEMM_STAGE_H;
        const __half* Bs = As + 128 * 72;

#pragma unroll
        for (int ks = 0; ks < 4; ++ks) {
            const int k = ks * 16;
            uint32_t af[2][4];
#pragma unroll
            for (int mf = 0; mf < 2; ++mf) {
                int rr = wm * 32 + mf * 16;
                af[mf][0] = *(const uint32_t*)&As[(rr + gid    ) * 72 + k + 2 * tig    ];
                af[mf][1] = *(const uint32_t*)&As[(rr + gid + 8) * 72 + k + 2 * tig    ];
                af[mf][2] = *(const uint32_t*)&As[(rr + gid    ) * 72 + k + 2 * tig + 8];
                af[mf][3] = *(const uint32_t*)&As[(rr + gid + 8) * 72 + k + 2 * tig + 8];
            }
            uint32_t bf[8][2];
#pragma unroll
            for (int nf = 0; nf < 8; ++nf) {
                int cc = wn * 64 + nf * 8;
                bf[nf][0] = *(const uint32_t*)&Bs[(cc + gid) * 72 + k + 2 * tig    ];
                bf[nf][1] = *(const uint32_t*)&Bs[(cc + gid) * 72 + k + 2 * tig + 8];
            }
#pragma unroll
            for (int mf = 0; mf < 2; ++mf)
#pragma unroll
                for (int nf = 0; nf < 8; ++nf)
                    mma16(acc[mf][nf], af[mf], bf[nf]);
        }
    }

#pragma unroll
    for (int mf = 0; mf < 2; ++mf) {
#pragma unroll
        for (int nf = 0; nf < 8; ++nf) {
            int col  = n0 + wn * 64 + nf * 8 + tig * 2;
            float b0 = bias[col], b1 = bias[col + 1];
            int row0 = m0 + wm * 32 + mf * 16 + gid;
            if (MODE == 0) {
                float* C = (float*)Cv;
                float2 v0 = make_float2(acc[mf][nf][0] + b0, acc[mf][nf][1] + b1);
                float2 v1 = make_float2(acc[mf][nf][2] + b0, acc[mf][nf][3] + b1);
                *(float2*)(C + (size_t)row0 * N + col)       = v0;
                *(float2*)(C + (size_t)(row0 + 8) * N + col) = v1;
            } else {
                __half* C = (__half*)Cv;
                __half2 v0 = __floats2half2_rn(acc[mf][nf][0] + b0, acc[mf][nf][1] + b1);
                __half2 v1 = __floats2half2_rn(acc[mf][nf][2] + b0, acc[mf][nf][3] + b1);
                int b  = row0 >> 11;
                int hh = col >> 6;
                size_t i0 = (((size_t)b * H_ + hh) * T_ + (row0 & 2047)) * HD_ + (col & 63);
                size_t i1 = (((size_t)b * H_ + hh) * T_ + ((row0 + 8) & 2047)) * HD_ + (col & 63);
                *(__half2*)(C + i0) = v0;
                *(__half2*)(C + i1) = v1;
            }
        }
    }
}

// ============================================================================
// Causal flash attention v4: register-resident softmax (FA-2 layout).
// Br=64, Bc=64, 8 warps. Warp (wm, wn): S rows [wm*16,+16) x kv [wn*32,+32).
// P stays in registers (sacc layout == PV A-frag layout); each warp keeps a
// PARTIAL O over its kv half, merged at epilogue. Row stats via quad shuffles
// + 2x64 smem exchange. Deferred l/m update -> 2 barriers per tile.
// Dynamic smem (bytes): Qs h 64x72 @0 | Ks h 2x64x72 | Vs h 2x64x72 |
//                       Os f32 64x68 (epilogue merge).  Total 63488.
// ============================================================================
#define AC_QS 0
#define AC_KS 9216
#define AC_VS (AC_KS + 2 * 9216)
#define AC_OS (AC_VS + 2 * 9216)
#define ATTN_SMEM_BYTES (AC_OS + 64 * 68 * 4)   // 63488

__global__ __launch_bounds__(256) void attn_flash(
    const __half* __restrict__ Q, const __half* __restrict__ K,
    const __half* __restrict__ V, __half* __restrict__ ctx)
{
    extern __shared__ char smc[];
    __half* Qs = (__half*)(smc + AC_QS);         // [64][72]
    __half* Ks = (__half*)(smc + AC_KS);         // 2 x [64][72]
    __half* Vs = (__half*)(smc + AC_VS);         // 2 x [64][72]
    float*  Os = (float*)(smc + AC_OS);          // [64][68] epilogue scratch
    __shared__ float mrow[64], lrow[64];
    __shared__ float pm[2][64], ps[2][64];

    const int tid  = threadIdx.x;
    const int warp = tid >> 5, lane = tid & 31;
    const int gid  = lane >> 2, tig = lane & 3;
    const int wm   = warp >> 1;        // 0..3 : rows [wm*16,+16)
    const int wn   = warp & 1;         // 0..1 : kv half [wn*32,+32)
    const int qt   = blockIdx.x;
    const int bh   = blockIdx.y;

    const int row_lo = wm * 16 + gid;
    const int row_hi = row_lo + 8;

    const __half* Qg = Q + (size_t)bh * T_ * HD_ + (size_t)qt * 64 * HD_;
    const __half* Kg = K + (size_t)bh * T_ * HD_;
    const __half* Vg = V + (size_t)bh * T_ * HD_;

    // load Q tile
    {
#pragma unroll
        for (int i = 0; i < 2; ++i) {
            int f = tid + 256 * i;
            int r = f >> 3, ch = f & 7;
            *(uint4*)(Qs + r * 72 + ch * 8) = *(const uint4*)(Qg + (size_t)r * HD_ + ch * 8);
        }
    }
    if (tid < 64) { mrow[tid] = -1e30f; lrow[tid] = 0.f; }

    auto issue_kv = [&](int t, int s) {
        const __half* Kt = Kg + (size_t)t * 64 * HD_;
        const __half* Vt = Vg + (size_t)t * 64 * HD_;
        __half* Kd = Ks + (size_t)s * (64 * 72);
        __half* Vd = Vs + (size_t)s * (64 * 72);
#pragma unroll
        for (int i = 0; i < 2; ++i) {
            int f = tid + 256 * i;
            int r = f >> 3, ch = f & 7;
            cp16((uint32_t)__cvta_generic_to_shared(Kd + r * 72 + ch * 8),
                 Kt + (size_t)r * HD_ + ch * 8);
            cp16((uint32_t)__cvta_generic_to_shared(Vd + r * 72 + ch * 8),
                 Vt + (size_t)r * HD_ + ch * 8);
        }
    };

    float oacc[8][4];      // partial O: rows (gid, gid+8) x hd cols nf*8+2tig(+1)
#pragma unroll
    for (int i = 0; i < 8; i++)
#pragma unroll
        for (int j = 0; j < 4; j++) oacc[i][j] = 0.f;

    float f_lo = 1.f, f_hi = 1.f, mn_lo = -1e30f, mn_hi = -1e30f;

    const int nkv = qt + 1;
    issue_kv(0, 0); cp_commit();

    for (int t = 0; t < nkv; ++t) {
        const int buf = t & 1;
        cp_wait0();
        __syncthreads();                       // kv ready; prev ps/pm visible

        // deferred l/m update for tile t-1 (designated: wn==0, tig==0)
        if (t > 0 && wn == 0 && tig == 0) {
            lrow[row_lo] = lrow[row_lo] * f_lo + ps[0][row_lo] + ps[1][row_lo];
            lrow[row_hi] = lrow[row_hi] * f_hi + ps[0][row_hi] + ps[1][row_hi];
            mrow[row_lo] = mn_lo;
            mrow[row_hi] = mn_hi;
        }
        if (t + 1 < nkv) { issue_kv(t + 1, buf ^ 1); cp_commit(); }

        const __half* Kb = Ks + (size_t)buf * (64 * 72);
        const __half* Vb = Vs + (size_t)buf * (64 * 72);

        // ---- S = Q @ K^T : rows [wm*16,+16), kv cols [wn*32,+32) ----
        float sacc[4][4];
#pragma unroll
        for (int i = 0; i < 4; i++)
#pragma unroll
            for (int j = 0; j < 4; j++) sacc[i][j] = 0.f;

#pragma unroll
        for (int ks = 0; ks < 4; ++ks) {
            const int k = ks * 16;
            uint32_t af[4];
            int rr = wm * 16;
            af[0] = *(const uint32_t*)&Qs[(rr + gid    ) * 72 + k + 2 * tig    ];
            af[1] = *(const uint32_t*)&Qs[(rr + gid + 8) * 72 + k + 2 * tig    ];
            af[2] = *(const uint32_t*)&Qs[(rr + gid    ) * 72 + k + 2 * tig + 8];
            af[3] = *(const uint32_t*)&Qs[(rr + gid + 8) * 72 + k + 2 * tig + 8];
#pragma unroll
            for (int nf = 0; nf < 4; ++nf) {
                int cc = wn * 32 + nf * 8;
                uint32_t bf[2];
                bf[0] = *(const uint32_t*)&Kb[(cc + gid) * 72 + k + 2 * tig    ];
                bf[1] = *(const uint32_t*)&Kb[(cc + gid) * 72 + k + 2 * tig + 8];
                mma16(sacc[nf], af, bf);
            }
        }

        // ---- scale + mask in registers ----
        if (t == qt) {
            const int grow_lo = qt * 64 + row_lo;
            const int grow_hi = qt * 64 + row_hi;
#pragma unroll
            for (int nf = 0; nf < 4; ++nf) {
                int c0 = t * 64 + wn * 32 + nf * 8 + 2 * tig;
                sacc[nf][0] = (c0     <= grow_lo) ? sacc[nf][0] * SCALE_ : -1e30f;
                sacc[nf][1] = (c0 + 1 <= grow_lo) ? sacc[nf][1] * SCALE_ : -1e30f;
                sacc[nf][2] = (c0     <= grow_hi) ? sacc[nf][2] * SCALE_ : -1e30f;
                sacc[nf][3] = (c0 + 1 <= grow_hi) ? sacc[nf][3] * SCALE_ : -1e30f;
            }
        } else {
#pragma unroll
            for (int nf = 0; nf < 4; ++nf)
#pragma unroll
                for (int j = 0; j < 4; ++j) sacc[nf][j] *= SCALE_;
        }

        // ---- row max over warp's 32 cols (quad shuffles) ----
        float m_lo = -1e30f, m_hi = -1e30f;
#pragma unroll
        for (int nf = 0; nf < 4; ++nf) {
            m_lo = fmaxf(m_lo, fmaxf(sacc[nf][0], sacc[nf][1]));
            m_hi = fmaxf(m_hi, fmaxf(sacc[nf][2], sacc[nf][3]));
        }
        m_lo = fmaxf(m_lo, __shfl_xor_sync(0xffffffffu, m_lo, 1));
        m_lo = fmaxf(m_lo, __shfl_xor_sync(0xffffffffu, m_lo, 2));
        m_hi = fmaxf(m_hi, __shfl_xor_sync(0xffffffffu, m_hi, 1));
        m_hi = fmaxf(m_hi, __shfl_xor_sync(0xffffffffu, m_hi, 2));
        if (tig == 0) { pm[wn][row_lo] = m_lo; pm[wn][row_hi] = m_hi; }
        __syncthreads();                       // pm exchange

        // ---- new stats, exp in registers, P -> fp16 frags ----
        float mold_lo = mrow[row_lo], mold_hi = mrow[row_hi];
        mn_lo = fmaxf(mold_lo, fmaxf(pm[0][row_lo], pm[1][row_lo]));
        mn_hi = fmaxf(mold_hi, fmaxf(pm[0][row_hi], pm[1][row_hi]));
        f_lo  = __expf(mold_lo - mn_lo);
        f_hi  = __expf(mold_hi - mn_hi);

        float s_lo = 0.f, s_hi = 0.f;
        uint32_t ph[4][2];   // [nf]: half2 for (row_lo pair, row_hi pair)
#pragma unroll
        for (int nf = 0; nf < 4; ++nf) {
            float p0 = __expf(sacc[nf][0] - mn_lo);
            float p1 = __expf(sacc[nf][1] - mn_lo);
            float p2 = __expf(sacc[nf][2] - mn_hi);
            float p3 = __expf(sacc[nf][3] - mn_hi);
            s_lo += p0 + p1;
            s_hi += p2 + p3;
            ph[nf][0] = h2pack(p0, p1);
            ph[nf][1] = h2pack(p2, p3);
        }
        s_lo += __shfl_xor_sync(0xffffffffu, s_lo, 1);
        s_lo += __shfl_xor_sync(0xffffffffu, s_lo, 2);
        s_hi += __shfl_xor_sync(0xffffffffu, s_hi, 1);
        s_hi += __shfl_xor_sync(0xffffffffu, s_hi, 2);
        if (tig == 0) { ps[wn][row_lo] = s_lo; ps[wn][row_hi] = s_hi; }

        // ---- rescale partial O, then O += P @ V (own kv half) ----
#pragma unroll
        for (int nf = 0; nf < 8; ++nf) {
            oacc[nf][0] *= f_lo; oacc[nf][1] *= f_lo;
            oacc[nf][2] *= f_hi; oacc[nf][3] *= f_hi;
        }
        const int g8 = lane >> 3;              // ldmatrix group 0..3
        const int r8 = lane & 7;
#pragma unroll
        for (int ksp = 0; ksp < 2; ++ksp) {
            uint32_t af[4];
            af[0] = ph[2 * ksp    ][0];
            af[1] = ph[2 * ksp    ][1];
            af[2] = ph[2 * ksp + 1][0];
            af[3] = ph[2 * ksp + 1][1];
            const int kbase = wn * 32 + ksp * 16;
#pragma unroll
            for (int nfp = 0; nfp < 4; ++nfp) {
                // x4.trans: mats (k0-7,n0),(k8-15,n0),(k0-7,n1),(k8-15,n1)
                uint32_t vaddr = (uint32_t)__cvta_generic_to_shared(
                    Vb + (size_t)(kbase + (g8 & 1) * 8 + r8) * 72 + (nfp * 2 + (g8 >> 1)) * 8);
                uint32_t b0, b1, b2, b3;
                ldsm_x4_trans(b0, b1, b2, b3, vaddr);
                uint32_t bfa[2] = { b0, b1 };
                uint32_t bfb[2] = { b2, b3 };
                mma16(oacc[nfp * 2    ], af, bfa);
                mma16(oacc[nfp * 2 + 1], af, bfb);
            }
        }
    }

    // ---- final l update, merge partials, write ctx ----
    __syncthreads();                           // last ps visible
    if (wn == 0 && tig == 0) {
        lrow[row_lo] = lrow[row_lo] * f_lo + ps[0][row_lo] + ps[1][row_lo];
        lrow[row_hi] = lrow[row_hi] * f_hi + ps[0][row_hi] + ps[1][row_hi];
    }
    if (wn == 1) {
#pragma unroll
        for (int nf = 0; nf < 8; ++nf) {
            int col = nf * 8 + 2 * tig;
            Os[row_lo * 68 + col]     = oacc[nf][0];
            Os[row_lo * 68 + col + 1] = oacc[nf][1];
            Os[row_hi * 68 + col]     = oacc[nf][2];
            Os[row_hi * 68 + col + 1] = oacc[nf][3];
        }
    }
    __syncthreads();
    if (wn == 0) {
        float il_lo = 1.f / lrow[row_lo];
        float il_hi = 1.f / lrow[row_hi];
        int b = bh >> 5, h = bh & 31;
        size_t base = ((size_t)b * T_ + (size_t)qt * 64) * D_ + h * 64;
#pragma unroll
        for (int nf = 0; nf < 8; ++nf) {
            int col = nf * 8 + 2 * tig;
            float o0 = (oacc[nf][0] + Os[row_lo * 68 + col])     * il_lo;
            float o1 = (oacc[nf][1] + Os[row_lo * 68 + col + 1]) * il_lo;
            float o2 = (oacc[nf][2] + Os[row_hi * 68 + col])     * il_hi;
            float o3 = (oacc[nf][3] + Os[row_hi * 68 + col + 1]) * il_hi;
            __half2 v0 = __floats2half2_rn(o0, o1);
            __half2 v1 = __floats2half2_rn(o2, o3);
            *(__half2*)(ctx + base + (size_t)row_lo * D_ + col) = v0;
            *(__half2*)(ctx + base + (size_t)row_hi * D_ + col) = v1;
        }
    }
}

// ============================================================================
extern "C" void kernel_launch(void* const* d_in, const int* in_sizes, int n_in,
                              void* d_out, int out_size)
{
    (void)in_sizes; (void)n_in; (void)out_size;
    const float* X  = (const float*)d_in[0];
    const float* Wq = (const float*)d_in[1];
    const float* bq = (const float*)d_in[2];
    const float* Wk = (const float*)d_in[3];
    const float* bk = (const float*)d_in[4];
    const float* Wv = (const float*)d_in[5];
    const float* bv = (const float*)d_in[6];
    const float* Wo = (const float*)d_in[7];
    const float* bo = (const float*)d_in[8];
    float* out = (float*)d_out;

    __half *x, *wq, *wk, *wv, *wo, *q, *k, *v, *ctx;
    cudaGetSymbolAddress((void**)&x,   g_x);
    cudaGetSymbolAddress((void**)&wq,  g_wq);
    cudaGetSymbolAddress((void**)&wk,  g_wk);
    cudaGetSymbolAddress((void**)&wv,  g_wv);
    cudaGetSymbolAddress((void**)&wo,  g_wo);
    cudaGetSymbolAddress((void**)&q,   g_q);
    cudaGetSymbolAddress((void**)&k,   g_k);
    cudaGetSymbolAddress((void**)&v,   g_v);
    cudaGetSymbolAddress((void**)&ctx, g_ctx);

    cudaFuncSetAttribute(gemm_f16<0>, cudaFuncAttributeMaxDynamicSharedMemorySize, GEMM_SMEM_BYTES);
    cudaFuncSetAttribute(gemm_f16<1>, cudaFuncAttributeMaxDynamicSharedMemorySize, GEMM_SMEM_BYTES);
    cudaFuncSetAttribute(attn_flash,  cudaFuncAttributeMaxDynamicSharedMemorySize, ATTN_SMEM_BYTES);

    // convert activations + weights to fp16
    const int nx4 = B_ * T_ * D_ / 4;
    const int nw4 = D_ * D_ / 4;
    to_half_kernel<<<nx4 / 256, 256>>>((const float4*)X,  (uint2*)x,  nx4);
    to_half_kernel<<<nw4 / 256, 256>>>((const float4*)Wq, (uint2*)wq, nw4);
    to_half_kernel<<<nw4 / 256, 256>>>((const float4*)Wk, (uint2*)wk, nw4);
    to_half_kernel<<<nw4 / 256, 256>>>((const float4*)Wv, (uint2*)wv, nw4);
    to_half_kernel<<<nw4 / 256, 256>>>((const float4*)Wo, (uint2*)wo, nw4);

    const int M = B_ * T_;   // 4096
    const int N = D_;        // 2048
    const int K = D_;        // 2048
    dim3 gg(N / 128, M / 128);   // 16 x 32

    gemm_f16<1><<<gg, 256, GEMM_SMEM_BYTES>>>(x, wq, bq, q, M, N, K);
    gemm_f16<1><<<gg, 256, GEMM_SMEM_BYTES>>>(x, wk, bk, k, M, N, K);
    gemm_f16<1><<<gg, 256, GEMM_SMEM_BYTES>>>(x, wv, bv, v, M, N, K);

    attn_flash<<<dim3(T_ / 64, B_ * H_), 256, ATTN_SMEM_BYTES>>>(q, k, v, ctx);

    gemm_f16<0><<<gg, 256, GEMM_SMEM_BYTES>>>(ctx, wo, bo, out, M, N, K);
}